// round 7
// baseline (speedup 1.0000x reference)
#include <cuda_runtime.h>
#include <cuda_bf16.h>
#include <math.h>

#define BB 8
#define LL 1024
#define DD 512
#define HH 8
#define DKK 64

// Scratch (__device__ globals; no runtime allocation)
__device__ float g_Q[BB*HH*LL*DKK];   // (B,H,L,DK) fp32
__device__ float g_K[BB*HH*LL*DKK];
__device__ float g_V[BB*HH*LL*DKK];
__device__ float g_X[BB*LL*DD];       // attention output (B,L,D) fp32

// m16n8k16 bf16 MMA. A row-major (16x16), B col-major (16x8), C fp32.
__device__ __forceinline__ void mma16(float* c, const unsigned* a, unsigned b0, unsigned b1) {
    asm volatile(
        "mma.sync.aligned.m16n8k16.row.col.f32.bf16.bf16.f32 "
        "{%0,%1,%2,%3}, {%4,%5,%6,%7}, {%8,%9}, {%0,%1,%2,%3};\n"
        : "+f"(c[0]), "+f"(c[1]), "+f"(c[2]), "+f"(c[3])
        : "r"(a[0]), "r"(a[1]), "r"(a[2]), "r"(a[3]), "r"(b0), "r"(b1));
}

// pack two floats as bf16x2: lo 16 bits = first val, hi 16 bits = second val
__device__ __forceinline__ unsigned packbf(float lo_val, float hi_val) {
    unsigned d;
    asm("cvt.rn.bf16x2.f32 %0, %1, %2;" : "=r"(d) : "f"(hi_val), "f"(lo_val));
    return d;
}
// split a pair of floats into (hi bf16x2, lo bf16x2): x = hi + lo, ~16 mantissa bits
__device__ __forceinline__ void splitbf2(float xe, float xo, unsigned& h, unsigned& l) {
    h = packbf(xe, xo);
    float fe = __uint_as_float(h << 16);
    float fo = __uint_as_float(h & 0xffff0000u);
    l = packbf(xe - fe, xo - fo);
}

// ---------------------------------------------------------------------------
// 3xBF16 GEMM with fragment-major smem.
// C[m,n] = sum_k A[m,k]*W[n,k] + bias[n]. M=8192, N=512, K=512.
// Block 128x64, BK=32, 256 thr (8 warps, 4m x 2n), warp tile 32x32.
// smem: Af[(kt*128+row)*4+t] uint4 {ah_t, ah_t4, al_t, al_t4}  (16 KB)
//       Bf[(kt*64 +row)*4+t] uint4 {bh0, bh1, bl0, bl1}        ( 8 KB)
// One LDS.128 = full hi+lo fragment. Conflict-free by construction.
// ---------------------------------------------------------------------------
__global__ __launch_bounds__(256) void gemm_bf16(
    const float* __restrict__ A, const float* __restrict__ W,
    const float* __restrict__ bias, float* __restrict__ C, int headmode)
{
    __shared__ uint4 Af[2*128*4];   // 1024 uint4
    __shared__ uint4 Bf[2*64*4];    // 512 uint4
    unsigned* Au = (unsigned*)Af;
    unsigned* Bu = (unsigned*)Bf;

    const int tid  = threadIdx.x;
    const int lane = tid & 31;
    const int warp = tid >> 5;
    const int g = lane >> 2, t = lane & 3;
    const int wm = warp & 3, wn = warp >> 2;
    const int m0 = blockIdx.y << 7, n0 = blockIdx.x << 6;

    float c[2][4][4];
    #pragma unroll
    for (int mt = 0; mt < 2; mt++)
        #pragma unroll
        for (int nt = 0; nt < 4; nt++)
            #pragma unroll
            for (int k = 0; k < 4; k++) c[mt][nt][k] = 0.f;

    const float* Abase = A + (size_t)m0 * DD;
    const float* Wbase = W + (size_t)n0 * DD;

    float4 ra[4], rb[2];
    #pragma unroll
    for (int i = 0; i < 4; i++) {
        int idx = tid + (i << 8);
        ra[i] = *(const float4*)(Abase + (size_t)(idx >> 3) * DD + ((idx & 7) << 2));
    }
    #pragma unroll
    for (int i = 0; i < 2; i++) {
        int idx = tid + (i << 8);
        rb[i] = *(const float4*)(Wbase + (size_t)(idx >> 3) * DD + ((idx & 7) << 2));
    }

    for (int k0 = 0; k0 < DD; k0 += 32) {
        __syncthreads();
        #pragma unroll
        for (int i = 0; i < 4; i++) {
            int idx = tid + (i << 8);
            int row = idx >> 3, kp = (idx & 7) << 1;  // kp even
            unsigned h0, l0, h1, l1;
            splitbf2(ra[i].x, ra[i].y, h0, l0);       // kpair kp
            splitbf2(ra[i].z, ra[i].w, h1, l1);       // kpair kp+1
            {
                int kt = kp >> 3, tt = kp & 3, sl = (kp >> 2) & 1;
                int base = (((kt << 7) + row) * 4 + tt) * 4;
                Au[base + sl] = h0; Au[base + 2 + sl] = l0;
            }
            {
                int kq = kp + 1;
                int kt = kq >> 3, tt = kq & 3, sl = (kq >> 2) & 1;
                int base = (((kt << 7) + row) * 4 + tt) * 4;
                Au[base + sl] = h1; Au[base + 2 + sl] = l1;
            }
        }
        #pragma unroll
        for (int i = 0; i < 2; i++) {
            int idx = tid + (i << 8);
            int row = idx >> 3, kp = (idx & 7) << 1;
            unsigned h0, l0, h1, l1;
            splitbf2(rb[i].x, rb[i].y, h0, l0);
            splitbf2(rb[i].z, rb[i].w, h1, l1);
            {
                int kt = kp >> 3, tt = kp & 3, sl = (kp >> 2) & 1;
                int base = (((kt << 6) + row) * 4 + tt) * 4;
                Bu[base + sl] = h0; Bu[base + 2 + sl] = l0;
            }
            {
                int kq = kp + 1;
                int kt = kq >> 3, tt = kq & 3, sl = (kq >> 2) & 1;
                int base = (((kt << 6) + row) * 4 + tt) * 4;
                Bu[base + sl] = h1; Bu[base + 2 + sl] = l1;
            }
        }
        __syncthreads();

        if (k0 + 32 < DD) {
            #pragma unroll
            for (int i = 0; i < 4; i++) {
                int idx = tid + (i << 8);
                ra[i] = *(const float4*)(Abase + (size_t)(idx >> 3) * DD + k0 + 32 + ((idx & 7) << 2));
            }
            #pragma unroll
            for (int i = 0; i < 2; i++) {
                int idx = tid + (i << 8);
                rb[i] = *(const float4*)(Wbase + (size_t)(idx >> 3) * DD + k0 + 32 + ((idx & 7) << 2));
            }
        }

        #pragma unroll
        for (int kt = 0; kt < 2; kt++) {
            unsigned ah[2][4], al[2][4];
            #pragma unroll
            for (int mt = 0; mt < 2; mt++) {
                int r = wm * 32 + mt * 16 + g;
                uint4 U = Af[((kt << 7) + r    ) * 4 + t];
                uint4 Wd = Af[((kt << 7) + r + 8) * 4 + t];
                ah[mt][0] = U.x;  ah[mt][1] = Wd.x;  ah[mt][2] = U.y;  ah[mt][3] = Wd.y;
                al[mt][0] = U.z;  al[mt][1] = Wd.z;  al[mt][2] = U.w;  al[mt][3] = Wd.w;
            }
            #pragma unroll
            for (int nt = 0; nt < 4; nt++) {
                uint4 bb = Bf[((kt << 6) + wn * 32 + nt * 8 + g) * 4 + t];
                #pragma unroll
                for (int mt = 0; mt < 2; mt++) {
                    mma16(c[mt][nt], al[mt], bb.x, bb.y);
                    mma16(c[mt][nt], ah[mt], bb.z, bb.w);
                    mma16(c[mt][nt], ah[mt], bb.x, bb.y);
                }
            }
        }
    }

    // epilogue: bias + store
    #pragma unroll
    for (int nt = 0; nt < 4; nt++) {
        int n = n0 + wn * 32 + nt * 8 + 2 * t;
        float b0 = bias[n], b1 = bias[n + 1];
        #pragma unroll
        for (int mt = 0; mt < 2; mt++) {
            int m = m0 + wm * 32 + mt * 16 + g;
            if (headmode) {
                int b_ = m >> 10, l = m & 1023;
                int h = n >> 6, dk = n & 63;
                float* p0 = C + (((size_t)b_ * HH + h) * LL + l) * DKK + dk;
                float* p1 = C + (((size_t)b_ * HH + h) * LL + (l + 8)) * DKK + dk;
                *(float2*)p0 = make_float2(c[mt][nt][0] + b0, c[mt][nt][1] + b1);
                *(float2*)p1 = make_float2(c[mt][nt][2] + b0, c[mt][nt][3] + b1);
            } else {
                float* p0 = C + (size_t)m * DD + n;
                float* p1 = C + (size_t)(m + 8) * DD + n;
                *(float2*)p0 = make_float2(c[mt][nt][0] + b0, c[mt][nt][1] + b1);
                *(float2*)p1 = make_float2(c[mt][nt][2] + b0, c[mt][nt][3] + b1);
            }
        }
    }
}

// ---------------------------------------------------------------------------
// Flash attention, 3xBF16 m16n8k16, fragment-major smem, P fully in registers.
// Block = (bh, 64 q-rows), 128 threads (4 warps x 16 q-rows).
// smem: Kf, Vf each [4kt][64n][4t] uint4 {h0,h1,l0,l1} = 16 KB each; 32 KB total.
// P(C-frag)->A-frag is an in-lane register permutation: no smem, no sync.
// ---------------------------------------------------------------------------
#define QSP 68
#define SMEM_ATTN (2048 * (int)sizeof(uint4))   // 32768 B

__global__ __launch_bounds__(128, 3) void attn_bf16(
    const float* __restrict__ dist, const unsigned char* __restrict__ mask,
    const float* __restrict__ logwb)
{
    extern __shared__ uint4 smq[];
    uint4* Kf = smq;            // [4*64*4]
    uint4* Vf = smq + 1024;     // [4*64*4]
    unsigned* Ku = (unsigned*)Kf;
    unsigned* Vu = (unsigned*)Vf;
    float* Qstage = (float*)smq;   // overlay, used before first tile only

    const int tid  = threadIdx.x;
    const int lane = tid & 31;
    const int warp = tid >> 5;
    const int g = lane >> 2, t = lane & 3;

    const int bh = blockIdx.y;
    const int b  = bh >> 3, h = bh & 7;
    const int q0 = blockIdx.x << 6;

    const float wb = __expf(logwb[h]);

    // Stage Q (scaled 0.125) into smem overlay, then split into register frags.
    const float* Qg = g_Q + ((size_t)bh * LL + q0) * DKK;
    for (int i = tid; i < 1024; i += 128) {       // 64 rows x 16 float4
        int r = i >> 4, c4 = (i & 15) << 2;
        float4 v = *(const float4*)(Qg + (size_t)r * DKK + c4);
        v.x *= 0.125f; v.y *= 0.125f; v.z *= 0.125f; v.w *= 0.125f;
        *(float4*)&Qstage[r * QSP + c4] = v;
    }
    __syncthreads();

    unsigned qh[4][4], ql[4][4];
    {
        int r = warp * 16 + g;
        #pragma unroll
        for (int kt = 0; kt < 4; kt++) {
            int cb = kt*16 + 2*t;
            float2 f;
            f = *(const float2*)&Qstage[ r      * QSP + cb    ]; splitbf2(f.x, f.y, qh[kt][0], ql[kt][0]);
            f = *(const float2*)&Qstage[(r + 8) * QSP + cb    ]; splitbf2(f.x, f.y, qh[kt][1], ql[kt][1]);
            f = *(const float2*)&Qstage[ r      * QSP + cb + 8]; splitbf2(f.x, f.y, qh[kt][2], ql[kt][2]);
            f = *(const float2*)&Qstage[(r + 8) * QSP + cb + 8]; splitbf2(f.x, f.y, qh[kt][3], ql[kt][3]);
        }
    }

    float o[8][4];
    #pragma unroll
    for (int nt = 0; nt < 8; nt++)
        #pragma unroll
        for (int k = 0; k < 4; k++) o[nt][k] = 0.f;
    float mrow[2] = {-1e30f, -1e30f};
    float lrow[2] = {0.f, 0.f};

    const float* Kg = g_K + (size_t)bh * LL * DKK;
    const float* Vg = g_V + (size_t)bh * LL * DKK;
    const float* db = dist + (size_t)b * LL * LL;
    const unsigned char* mb = mask + (size_t)b * LL * LL;

    const int qr0 = q0 + warp * 16 + g;

    for (int k0 = 0; k0 < LL; k0 += 64) {
        __syncthreads();   // everyone done with previous Kf/Vf (and Qstage on iter 0)

        // K tile -> fragment-major: Kf[(kt*64+n)*4+t] = {bh0,bh1,bl0,bl1}
        for (int i = tid; i < 1024; i += 128) {
            int r = i >> 4, c4 = (i & 15) << 2;    // r = key row (n), kp = c4/2 even
            float4 kv = *(const float4*)(Kg + (size_t)(k0 + r) * DKK + c4);
            int kp = c4 >> 1;
            unsigned h0, l0, h1, l1;
            splitbf2(kv.x, kv.y, h0, l0);
            splitbf2(kv.z, kv.w, h1, l1);
            {
                int kt = kp >> 3, tt = kp & 3, sl = (kp >> 2) & 1;
                int base = (((kt << 6) + r) * 4 + tt) * 4;
                Ku[base + sl] = h0; Ku[base + 2 + sl] = l0;
            }
            {
                int kq = kp + 1;
                int kt = kq >> 3, tt = kq & 3, sl = (kq >> 2) & 1;
                int base = (((kt << 6) + r) * 4 + tt) * 4;
                Ku[base + sl] = h1; Ku[base + 2 + sl] = l1;
            }
        }
        // V tile -> fragment-major: Vf[(kt*64+n)*4+t] = {vh0,vh1,vl0,vl1}
        // vh at kpair kp packs V rows (2kp, 2kp+1) for column n.
        for (int i = tid; i < 512; i += 128) {
            int kp = i >> 4, c4 = (i & 15) << 2;
            float4 v0 = *(const float4*)(Vg + (size_t)(k0 + 2*kp    ) * DKK + c4);
            float4 v1 = *(const float4*)(Vg + (size_t)(k0 + 2*kp + 1) * DKK + c4);
            int kt = kp >> 3, tt = kp & 3, sl = (kp >> 2) & 1;
            unsigned hh, llv;
            splitbf2(v0.x, v1.x, hh, llv);
            { int base = (((kt << 6) + c4    ) * 4 + tt) * 4; Vu[base + sl] = hh; Vu[base + 2 + sl] = llv; }
            splitbf2(v0.y, v1.y, hh, llv);
            { int base = (((kt << 6) + c4 + 1) * 4 + tt) * 4; Vu[base + sl] = hh; Vu[base + 2 + sl] = llv; }
            splitbf2(v0.z, v1.z, hh, llv);
            { int base = (((kt << 6) + c4 + 2) * 4 + tt) * 4; Vu[base + sl] = hh; Vu[base + 2 + sl] = llv; }
            splitbf2(v0.w, v1.w, hh, llv);
            { int base = (((kt << 6) + c4 + 3) * 4 + tt) * 4; Vu[base + sl] = hh; Vu[base + 2 + sl] = llv; }
        }
        __syncthreads();

        // S = Q @ K^T (3xBF16), one LDS.128 per (kt, nt)
        float s[8][4];
        #pragma unroll
        for (int nt = 0; nt < 8; nt++)
            #pragma unroll
            for (int k = 0; k < 4; k++) s[nt][k] = 0.f;

        #pragma unroll
        for (int kt = 0; kt < 4; kt++) {
            #pragma unroll
            for (int nt = 0; nt < 8; nt++) {
                uint4 kb = Kf[((kt << 6) + nt*8 + g) * 4 + t];
                mma16(s[nt], ql[kt], kb.x, kb.y);
                mma16(s[nt], qh[kt], kb.z, kb.w);
                mma16(s[nt], qh[kt], kb.x, kb.y);
            }
        }

        // distance bias + mask on C-fragments
        #pragma unroll
        for (int nt = 0; nt < 8; nt++) {
            int col = k0 + nt*8 + 2*t;
            float2 d0 = *(const float2*)(db + (size_t)qr0 * LL + col);
            float2 d1 = *(const float2*)(db + (size_t)(qr0 + 8) * LL + col);
            unsigned short mk0 = *(const unsigned short*)(mb + (size_t)qr0 * LL + col);
            unsigned short mk1 = *(const unsigned short*)(mb + (size_t)(qr0 + 8) * LL + col);
            s[nt][0] -= d0.x * wb; if (mk0 & 0xffu) s[nt][0] = -1e9f;
            s[nt][1] -= d0.y * wb; if (mk0 >> 8)    s[nt][1] = -1e9f;
            s[nt][2] -= d1.x * wb; if (mk1 & 0xffu) s[nt][2] = -1e9f;
            s[nt][3] -= d1.y * wb; if (mk1 >> 8)    s[nt][3] = -1e9f;
        }

        // online softmax
        #pragma unroll
        for (int i = 0; i < 2; i++) {
            float mx = -1e30f;
            #pragma unroll
            for (int nt = 0; nt < 8; nt++)
                mx = fmaxf(mx, fmaxf(s[nt][2*i], s[nt][2*i + 1]));
            mx = fmaxf(mx, __shfl_xor_sync(0xffffffffu, mx, 1));
            mx = fmaxf(mx, __shfl_xor_sync(0xffffffffu, mx, 2));
            float mnew  = fmaxf(mrow[i], mx);
            float alpha = __expf(mrow[i] - mnew);
            float sum = 0.f;
            #pragma unroll
            for (int nt = 0; nt < 8; nt++) {
                s[nt][2*i]     = __expf(s[nt][2*i]     - mnew);
                s[nt][2*i + 1] = __expf(s[nt][2*i + 1] - mnew);
                sum += s[nt][2*i] + s[nt][2*i + 1];
            }
            sum += __shfl_xor_sync(0xffffffffu, sum, 1);
            sum += __shfl_xor_sync(0xffffffffu, sum, 2);
            lrow[i] = lrow[i] * alpha + sum;
            mrow[i] = mnew;
            #pragma unroll
            for (int nt = 0; nt < 8; nt++) {
                o[nt][2*i]     *= alpha;
                o[nt][2*i + 1] *= alpha;
            }
        }

        // O += P @ V (3xBF16); P A-frags are an in-lane permutation of s[][].
        #pragma unroll
        for (int kt = 0; kt < 4; kt++) {
            unsigned pah[4], pal[4];
            splitbf2(s[2*kt  ][0], s[2*kt  ][1], pah[0], pal[0]);
            splitbf2(s[2*kt  ][2], s[2*kt  ][3], pah[1], pal[1]);
            splitbf2(s[2*kt+1][0], s[2*kt+1][1], pah[2], pal[2]);
            splitbf2(s[2*kt+1][2], s[2*kt+1][3], pah[3], pal[3]);
            #pragma unroll
            for (int nt = 0; nt < 8; nt++) {
                uint4 vb = Vf[((kt << 6) + nt*8 + g) * 4 + t];
                mma16(o[nt], pah, vb.z, vb.w);
                mma16(o[nt], pal, vb.x, vb.y);
                mma16(o[nt], pah, vb.x, vb.y);
            }
        }
    }

    // normalize + write X (B,L,D)
    float inv0 = 1.0f / lrow[0], inv1 = 1.0f / lrow[1];
    float* X0 = g_X + ((size_t)b * LL + qr0)     * DD + h * DKK;
    float* X1 = g_X + ((size_t)b * LL + qr0 + 8) * DD + h * DKK;
    #pragma unroll
    for (int nt = 0; nt < 8; nt++) {
        *(float2*)&X0[nt*8 + 2*t] = make_float2(o[nt][0] * inv0, o[nt][1] * inv0);
        *(float2*)&X1[nt*8 + 2*t] = make_float2(o[nt][2] * inv1, o[nt][3] * inv1);
    }
}

// ---------------------------------------------------------------------------
extern "C" void kernel_launch(void* const* d_in, const int* in_sizes, int n_in,
                              void* d_out, int out_size)
{
    const float* query = (const float*)d_in[0];
    const float* key   = (const float*)d_in[1];
    const float* value = (const float*)d_in[2];
    const float* dist  = (const float*)d_in[3];
    const unsigned char* mask = (const unsigned char*)d_in[4];
    const float* Wq = (const float*)d_in[5];
    const float* bq = (const float*)d_in[6];
    const float* Wk = (const float*)d_in[7];
    const float* bk = (const float*)d_in[8];
    const float* Wv = (const float*)d_in[9];
    const float* bv = (const float*)d_in[10];
    const float* Wo = (const float*)d_in[11];
    const float* bo = (const float*)d_in[12];
    const float* logwb = (const float*)d_in[13];

    void *pQ, *pK, *pV, *pX;
    cudaGetSymbolAddress(&pQ, g_Q);
    cudaGetSymbolAddress(&pK, g_K);
    cudaGetSymbolAddress(&pV, g_V);
    cudaGetSymbolAddress(&pX, g_X);

    cudaFuncSetAttribute(attn_bf16,
                         cudaFuncAttributeMaxDynamicSharedMemorySize, SMEM_ATTN);

    dim3 gg(DD / 64, (BB * LL) / 128);   // (8, 64)
    gemm_bf16<<<gg, 256>>>(query, Wq, bq, (float*)pQ, 1);
    gemm_bf16<<<gg, 256>>>(key,   Wk, bk, (float*)pK, 1);
    gemm_bf16<<<gg, 256>>>(value, Wv, bv, (float*)pV, 1);

    attn_bf16<<<dim3(LL / 64, BB * HH), 128, SMEM_ATTN>>>(dist, mask, logwb);

    gemm_bf16<<<gg, 256>>>((const float*)pX, Wo, bo, (float*)d_out, 0);
}

// round 8
// speedup vs baseline: 1.3355x; 1.3355x over previous
#include <cuda_runtime.h>
#include <cuda_bf16.h>
#include <math.h>

#define BB 8
#define LL 1024
#define DD 512
#define HH 8
#define DKK 64

// Scratch (__device__ globals; no runtime allocation)
__device__ float g_Q[BB*HH*LL*DKK];   // (B,H,L,DK) fp32
__device__ float g_K[BB*HH*LL*DKK];
__device__ float g_V[BB*HH*LL*DKK];
__device__ float g_X[BB*LL*DD];       // attention output (B,L,D) fp32

// m16n8k16 bf16 MMA. A row-major (16x16), B col-major (16x8), C fp32.
__device__ __forceinline__ void mma16(float* c, const unsigned* a, unsigned b0, unsigned b1) {
    asm volatile(
        "mma.sync.aligned.m16n8k16.row.col.f32.bf16.bf16.f32 "
        "{%0,%1,%2,%3}, {%4,%5,%6,%7}, {%8,%9}, {%0,%1,%2,%3};\n"
        : "+f"(c[0]), "+f"(c[1]), "+f"(c[2]), "+f"(c[3])
        : "r"(a[0]), "r"(a[1]), "r"(a[2]), "r"(a[3]), "r"(b0), "r"(b1));
}

// pack two floats as bf16x2: lo 16 bits = first val, hi 16 bits = second val
__device__ __forceinline__ unsigned packbf(float lo_val, float hi_val) {
    unsigned d;
    asm("cvt.rn.bf16x2.f32 %0, %1, %2;" : "=r"(d) : "f"(hi_val), "f"(lo_val));
    return d;
}
// split a pair of floats into (hi bf16x2, lo bf16x2): x = hi + lo, ~16 mantissa bits
__device__ __forceinline__ void splitbf2(float xe, float xo, unsigned& h, unsigned& l) {
    h = packbf(xe, xo);
    float fe = __uint_as_float(h << 16);
    float fo = __uint_as_float(h & 0xffff0000u);
    l = packbf(xe - fe, xo - fo);
}

// ---------------------------------------------------------------------------
// 3xBF16 GEMM (R6-proven): C[m,n] = sum_k A[m,k]*W[n,k] + bias[n]
// M=8192, N=512, K=512. Block 128x64, BK=32, 256 thr (8 warps, 4m x 2n),
// warp tile 32x32 = 2 mt x 4 nt of m16n8k16; 3 MMAs per frag (hi/lo split).
// smem: Ah/Al [128][20] words + Bh/Bl [64][20] words = 30,720 B (static).
// Stride 20: conflict-free for both uint2 fills and scalar frag loads.
// ---------------------------------------------------------------------------
#define GP 20

__global__ __launch_bounds__(256) void gemm_bf16(
    const float* __restrict__ A, const float* __restrict__ W,
    const float* __restrict__ bias, float* __restrict__ C, int headmode)
{
    __shared__ unsigned Ah[128*GP], Al[128*GP], Bh[64*GP], Bl[64*GP];

    const int tid  = threadIdx.x;
    const int lane = tid & 31;
    const int warp = tid >> 5;
    const int g = lane >> 2, t = lane & 3;
    const int wm = warp & 3, wn = warp >> 2;
    const int m0 = blockIdx.y << 7, n0 = blockIdx.x << 6;

    float c[2][4][4];
    #pragma unroll
    for (int mt = 0; mt < 2; mt++)
        #pragma unroll
        for (int nt = 0; nt < 4; nt++)
            #pragma unroll
            for (int k = 0; k < 4; k++) c[mt][nt][k] = 0.f;

    const float* Abase = A + (size_t)m0 * DD;
    const float* Wbase = W + (size_t)n0 * DD;

    float4 ra[4], rb[2];
    #pragma unroll
    for (int i = 0; i < 4; i++) {
        int idx = tid + (i << 8);
        ra[i] = *(const float4*)(Abase + (size_t)(idx >> 3) * DD + ((idx & 7) << 2));
    }
    #pragma unroll
    for (int i = 0; i < 2; i++) {
        int idx = tid + (i << 8);
        rb[i] = *(const float4*)(Wbase + (size_t)(idx >> 3) * DD + ((idx & 7) << 2));
    }

    for (int k0 = 0; k0 < DD; k0 += 32) {
        __syncthreads();
        #pragma unroll
        for (int i = 0; i < 4; i++) {
            int idx = tid + (i << 8);
            int row = idx >> 3, kp = (idx & 7) << 1;
            unsigned h0, l0, h1, l1;
            splitbf2(ra[i].x, ra[i].y, h0, l0);
            splitbf2(ra[i].z, ra[i].w, h1, l1);
            *(uint2*)&Ah[row*GP + kp] = make_uint2(h0, h1);
            *(uint2*)&Al[row*GP + kp] = make_uint2(l0, l1);
        }
        #pragma unroll
        for (int i = 0; i < 2; i++) {
            int idx = tid + (i << 8);
            int row = idx >> 3, kp = (idx & 7) << 1;
            unsigned h0, l0, h1, l1;
            splitbf2(rb[i].x, rb[i].y, h0, l0);
            splitbf2(rb[i].z, rb[i].w, h1, l1);
            *(uint2*)&Bh[row*GP + kp] = make_uint2(h0, h1);
            *(uint2*)&Bl[row*GP + kp] = make_uint2(l0, l1);
        }
        __syncthreads();

        if (k0 + 32 < DD) {
            #pragma unroll
            for (int i = 0; i < 4; i++) {
                int idx = tid + (i << 8);
                ra[i] = *(const float4*)(Abase + (size_t)(idx >> 3) * DD + k0 + 32 + ((idx & 7) << 2));
            }
            #pragma unroll
            for (int i = 0; i < 2; i++) {
                int idx = tid + (i << 8);
                rb[i] = *(const float4*)(Wbase + (size_t)(idx >> 3) * DD + k0 + 32 + ((idx & 7) << 2));
            }
        }

        #pragma unroll
        for (int kt = 0; kt < 2; kt++) {
            unsigned ah[2][4], al[2][4];
            #pragma unroll
            for (int mt = 0; mt < 2; mt++) {
                int r = wm * 32 + mt * 16 + g;
                ah[mt][0] = Ah[ r      *GP + kt*8 + t    ];
                ah[mt][1] = Ah[(r + 8) *GP + kt*8 + t    ];
                ah[mt][2] = Ah[ r      *GP + kt*8 + t + 4];
                ah[mt][3] = Ah[(r + 8) *GP + kt*8 + t + 4];
                al[mt][0] = Al[ r      *GP + kt*8 + t    ];
                al[mt][1] = Al[(r + 8) *GP + kt*8 + t    ];
                al[mt][2] = Al[ r      *GP + kt*8 + t + 4];
                al[mt][3] = Al[(r + 8) *GP + kt*8 + t + 4];
            }
            #pragma unroll
            for (int nt = 0; nt < 4; nt++) {
                int r = wn * 32 + nt * 8 + g;
                unsigned bh0 = Bh[r*GP + kt*8 + t    ];
                unsigned bh1 = Bh[r*GP + kt*8 + t + 4];
                unsigned bl0 = Bl[r*GP + kt*8 + t    ];
                unsigned bl1 = Bl[r*GP + kt*8 + t + 4];
                #pragma unroll
                for (int mt = 0; mt < 2; mt++) {
                    mma16(c[mt][nt], al[mt], bh0, bh1);
                    mma16(c[mt][nt], ah[mt], bl0, bl1);
                    mma16(c[mt][nt], ah[mt], bh0, bh1);
                }
            }
        }
    }

    // epilogue: bias + store
    #pragma unroll
    for (int nt = 0; nt < 4; nt++) {
        int n = n0 + wn * 32 + nt * 8 + 2 * t;
        float b0 = bias[n], b1 = bias[n + 1];
        #pragma unroll
        for (int mt = 0; mt < 2; mt++) {
            int m = m0 + wm * 32 + mt * 16 + g;
            if (headmode) {
                int b_ = m >> 10, l = m & 1023;
                int h = n >> 6, dk = n & 63;
                float* p0 = C + (((size_t)b_ * HH + h) * LL + l) * DKK + dk;
                float* p1 = C + (((size_t)b_ * HH + h) * LL + (l + 8)) * DKK + dk;
                *(float2*)p0 = make_float2(c[mt][nt][0] + b0, c[mt][nt][1] + b1);
                *(float2*)p1 = make_float2(c[mt][nt][2] + b0, c[mt][nt][3] + b1);
            } else {
                float* p0 = C + (size_t)m * DD + n;
                float* p1 = C + (size_t)(m + 8) * DD + n;
                *(float2*)p0 = make_float2(c[mt][nt][0] + b0, c[mt][nt][1] + b1);
                *(float2*)p1 = make_float2(c[mt][nt][2] + b0, c[mt][nt][3] + b1);
            }
        }
    }
}

// ---------------------------------------------------------------------------
// Flash attention, 3xBF16 m16n8k16 (R6 layout + in-register P + hoisted dist).
// Block = (bh, 64 q-rows), 128 threads (4 warps x 16 q-rows).
// smem (words): Kh/Kl [64][36], Vh/Vl [32][72] = 36,864 B. No P smem:
// P C-frag -> A-frag is an in-lane register permutation (validated R7).
// dist/mask loads hoisted before the S-MMA loop to hide LDG latency.
// ---------------------------------------------------------------------------
#define KP 36
#define VP 72
#define QSP 68
#define SMEM_ATTN ((2*64*KP + 2*32*VP) * (int)sizeof(unsigned))   // 36,864 B

__global__ __launch_bounds__(128, 3) void attn_bf16(
    const float* __restrict__ dist, const unsigned char* __restrict__ mask,
    const float* __restrict__ logwb)
{
    extern __shared__ unsigned smu[];
    unsigned* Kh = smu;                 // [64][KP]
    unsigned* Kl = Kh + 64*KP;
    unsigned* Vh = Kl + 64*KP;          // [32][VP]
    unsigned* Vl = Vh + 32*VP;
    float* Qstage = (float*)smu;        // overlay (pre-loop only): 64*QSP=4352 words

    const int tid  = threadIdx.x;
    const int lane = tid & 31;
    const int warp = tid >> 5;
    const int g = lane >> 2, t = lane & 3;

    const int bh = blockIdx.y;
    const int b  = bh >> 3, h = bh & 7;
    const int q0 = blockIdx.x << 6;

    const float wb = __expf(logwb[h]);

    // Stage Q (scaled 0.125) into smem overlay, then split into register frags.
    const float* Qg = g_Q + ((size_t)bh * LL + q0) * DKK;
    for (int i = tid; i < 1024; i += 128) {       // 64 rows x 16 float4
        int r = i >> 4, c4 = (i & 15) << 2;
        float4 v = *(const float4*)(Qg + (size_t)r * DKK + c4);
        v.x *= 0.125f; v.y *= 0.125f; v.z *= 0.125f; v.w *= 0.125f;
        *(float4*)&Qstage[r * QSP + c4] = v;
    }
    __syncthreads();

    unsigned qh[4][4], ql[4][4];
    {
        int r = warp * 16 + g;
        #pragma unroll
        for (int kt = 0; kt < 4; kt++) {
            int cb = kt*16 + 2*t;
            float2 f;
            f = *(const float2*)&Qstage[ r      * QSP + cb    ]; splitbf2(f.x, f.y, qh[kt][0], ql[kt][0]);
            f = *(const float2*)&Qstage[(r + 8) * QSP + cb    ]; splitbf2(f.x, f.y, qh[kt][1], ql[kt][1]);
            f = *(const float2*)&Qstage[ r      * QSP + cb + 8]; splitbf2(f.x, f.y, qh[kt][2], ql[kt][2]);
            f = *(const float2*)&Qstage[(r + 8) * QSP + cb + 8]; splitbf2(f.x, f.y, qh[kt][3], ql[kt][3]);
        }
    }

    float o[8][4];
    #pragma unroll
    for (int nt = 0; nt < 8; nt++)
        #pragma unroll
        for (int k = 0; k < 4; k++) o[nt][k] = 0.f;
    float mrow[2] = {-1e30f, -1e30f};
    float lrow[2] = {0.f, 0.f};

    const float* Kg = g_K + (size_t)bh * LL * DKK;
    const float* Vg = g_V + (size_t)bh * LL * DKK;
    const float* db = dist + (size_t)b * LL * LL;
    const unsigned char* mb = mask + (size_t)b * LL * LL;

    const int qr0 = q0 + warp * 16 + g;

    for (int k0 = 0; k0 < LL; k0 += 64) {
        __syncthreads();   // all warps done with previous K/V (and Qstage on iter 0)
        // K tile: [64 n][32 kpair] hi/lo (uint2 stores, stride 36 conflict-free)
        for (int i = tid; i < 1024; i += 128) {
            int r = i >> 4, c4 = (i & 15) << 2;
            float4 kv = *(const float4*)(Kg + (size_t)(k0 + r) * DKK + c4);
            unsigned h0, l0, h1, l1;
            splitbf2(kv.x, kv.y, h0, l0);
            splitbf2(kv.z, kv.w, h1, l1);
            *(uint2*)&Kh[r*KP + (c4 >> 1)] = make_uint2(h0, h1);
            *(uint2*)&Kl[r*KP + (c4 >> 1)] = make_uint2(l0, l1);
        }
        // V tile: [32 kpair][64 n] hi/lo (uint4 stores, stride 72)
        for (int i = tid; i < 512; i += 128) {
            int kp = i >> 4, c4 = (i & 15) << 2;
            float4 v0 = *(const float4*)(Vg + (size_t)(k0 + 2*kp    ) * DKK + c4);
            float4 v1 = *(const float4*)(Vg + (size_t)(k0 + 2*kp + 1) * DKK + c4);
            unsigned h0,l0,h1,l1,h2,l2,h3,l3;
            splitbf2(v0.x, v1.x, h0, l0);
            splitbf2(v0.y, v1.y, h1, l1);
            splitbf2(v0.z, v1.z, h2, l2);
            splitbf2(v0.w, v1.w, h3, l3);
            *(uint4*)&Vh[kp*VP + c4] = make_uint4(h0, h1, h2, h3);
            *(uint4*)&Vl[kp*VP + c4] = make_uint4(l0, l1, l2, l3);
        }
        __syncthreads();

        // Hoisted dist/mask loads: in flight during the S-MMA loop.
        float2 d0a[8], d1a[8];
        unsigned short mk0a[8], mk1a[8];
        #pragma unroll
        for (int nt = 0; nt < 8; nt++) {
            int col = k0 + nt*8 + 2*t;
            d0a[nt] = *(const float2*)(db + (size_t)qr0 * LL + col);
            d1a[nt] = *(const float2*)(db + (size_t)(qr0 + 8) * LL + col);
            mk0a[nt] = *(const unsigned short*)(mb + (size_t)qr0 * LL + col);
            mk1a[nt] = *(const unsigned short*)(mb + (size_t)(qr0 + 8) * LL + col);
        }

        // S = Q @ K^T (3xBF16)
        float s[8][4];
        #pragma unroll
        for (int nt = 0; nt < 8; nt++)
            #pragma unroll
            for (int k = 0; k < 4; k++) s[nt][k] = 0.f;

        #pragma unroll
        for (int kt = 0; kt < 4; kt++) {
            #pragma unroll
            for (int nt = 0; nt < 8; nt++) {
                int br = (nt*8 + g) * KP + kt*8;
                unsigned bh0 = Kh[br + t], bh1 = Kh[br + t + 4];
                unsigned bl0 = Kl[br + t], bl1 = Kl[br + t + 4];
                mma16(s[nt], ql[kt], bh0, bh1);
                mma16(s[nt], qh[kt], bl0, bl1);
                mma16(s[nt], qh[kt], bh0, bh1);
            }
        }

        // distance bias + mask on C-fragments (values already in registers)
        #pragma unroll
        for (int nt = 0; nt < 8; nt++) {
            s[nt][0] -= d0a[nt].x * wb; if (mk0a[nt] & 0xffu) s[nt][0] = -1e9f;
            s[nt][1] -= d0a[nt].y * wb; if (mk0a[nt] >> 8)    s[nt][1] = -1e9f;
            s[nt][2] -= d1a[nt].x * wb; if (mk1a[nt] & 0xffu) s[nt][2] = -1e9f;
            s[nt][3] -= d1a[nt].y * wb; if (mk1a[nt] >> 8)    s[nt][3] = -1e9f;
        }

        // online softmax
        #pragma unroll
        for (int i = 0; i < 2; i++) {
            float mx = -1e30f;
            #pragma unroll
            for (int nt = 0; nt < 8; nt++)
                mx = fmaxf(mx, fmaxf(s[nt][2*i], s[nt][2*i + 1]));
            mx = fmaxf(mx, __shfl_xor_sync(0xffffffffu, mx, 1));
            mx = fmaxf(mx, __shfl_xor_sync(0xffffffffu, mx, 2));
            float mnew  = fmaxf(mrow[i], mx);
            float alpha = __expf(mrow[i] - mnew);
            float sum = 0.f;
            #pragma unroll
            for (int nt = 0; nt < 8; nt++) {
                s[nt][2*i]     = __expf(s[nt][2*i]     - mnew);
                s[nt][2*i + 1] = __expf(s[nt][2*i + 1] - mnew);
                sum += s[nt][2*i] + s[nt][2*i + 1];
            }
            sum += __shfl_xor_sync(0xffffffffu, sum, 1);
            sum += __shfl_xor_sync(0xffffffffu, sum, 2);
            lrow[i] = lrow[i] * alpha + sum;
            mrow[i] = mnew;
            #pragma unroll
            for (int nt = 0; nt < 8; nt++) {
                o[nt][2*i]     *= alpha;
                o[nt][2*i + 1] *= alpha;
            }
        }

        // O += P @ V (3xBF16); P A-frags via in-lane permutation of s[][].
        // pah[0]=s[2kt][0:1] (row g), pah[1]=s[2kt][2:3] (row g+8),
        // pah[2]=s[2kt+1][0:1], pah[3]=s[2kt+1][2:3]   (validated in R7)
        #pragma unroll
        for (int kt = 0; kt < 4; kt++) {
            unsigned pah[4], pal[4];
            splitbf2(s[2*kt  ][0], s[2*kt  ][1], pah[0], pal[0]);
            splitbf2(s[2*kt  ][2], s[2*kt  ][3], pah[1], pal[1]);
            splitbf2(s[2*kt+1][0], s[2*kt+1][1], pah[2], pal[2]);
            splitbf2(s[2*kt+1][2], s[2*kt+1][3], pah[3], pal[3]);
            #pragma unroll
            for (int nt = 0; nt < 8; nt++) {
                unsigned vh0 = Vh[(kt*8 + t    ) * VP + nt*8 + g];
                unsigned vh1 = Vh[(kt*8 + t + 4) * VP + nt*8 + g];
                unsigned vl0 = Vl[(kt*8 + t    ) * VP + nt*8 + g];
                unsigned vl1 = Vl[(kt*8 + t + 4) * VP + nt*8 + g];
                mma16(o[nt], pah, vl0, vl1);
                mma16(o[nt], pal, vh0, vh1);
                mma16(o[nt], pah, vh0, vh1);
            }
        }
    }

    // normalize + write X (B,L,D)
    float inv0 = 1.0f / lrow[0], inv1 = 1.0f / lrow[1];
    float* X0 = g_X + ((size_t)b * LL + qr0)     * DD + h * DKK;
    float* X1 = g_X + ((size_t)b * LL + qr0 + 8) * DD + h * DKK;
    #pragma unroll
    for (int nt = 0; nt < 8; nt++) {
        *(float2*)&X0[nt*8 + 2*t] = make_float2(o[nt][0] * inv0, o[nt][1] * inv0);
        *(float2*)&X1[nt*8 + 2*t] = make_float2(o[nt][2] * inv1, o[nt][3] * inv1);
    }
}

// ---------------------------------------------------------------------------
extern "C" void kernel_launch(void* const* d_in, const int* in_sizes, int n_in,
                              void* d_out, int out_size)
{
    const float* query = (const float*)d_in[0];
    const float* key   = (const float*)d_in[1];
    const float* value = (const float*)d_in[2];
    const float* dist  = (const float*)d_in[3];
    const unsigned char* mask = (const unsigned char*)d_in[4];
    const float* Wq = (const float*)d_in[5];
    const float* bq = (const float*)d_in[6];
    const float* Wk = (const float*)d_in[7];
    const float* bk = (const float*)d_in[8];
    const float* Wv = (const float*)d_in[9];
    const float* bv = (const float*)d_in[10];
    const float* Wo = (const float*)d_in[11];
    const float* bo = (const float*)d_in[12];
    const float* logwb = (const float*)d_in[13];

    void *pQ, *pK, *pV, *pX;
    cudaGetSymbolAddress(&pQ, g_Q);
    cudaGetSymbolAddress(&pK, g_K);
    cudaGetSymbolAddress(&pV, g_V);
    cudaGetSymbolAddress(&pX, g_X);

    cudaFuncSetAttribute(attn_bf16,
                         cudaFuncAttributeMaxDynamicSharedMemorySize, SMEM_ATTN);

    dim3 gg(DD / 64, (BB * LL) / 128);   // (8, 64)
    gemm_bf16<<<gg, 256>>>(query, Wq, bq, (float*)pQ, 1);
    gemm_bf16<<<gg, 256>>>(key,   Wk, bk, (float*)pK, 1);
    gemm_bf16<<<gg, 256>>>(value, Wv, bv, (float*)pV, 1);

    attn_bf16<<<dim3(LL / 64, BB * HH), 128, SMEM_ATTN>>>(dist, mask, logwb);

    gemm_bf16<<<gg, 256>>>((const float*)pX, Wo, bo, (float*)d_out, 0);
}

// round 9
// speedup vs baseline: 1.4801x; 1.1083x over previous
#include <cuda_runtime.h>
#include <cuda_bf16.h>
#include <math.h>

#define BB 8
#define LL 1024
#define DD 512
#define HH 8
#define DKK 64

// Scratch (__device__ globals; no runtime allocation)
__device__ float g_Q[BB*HH*LL*DKK];   // (B,H,L,DK) fp32
__device__ float g_K[BB*HH*LL*DKK];
__device__ float g_V[BB*HH*LL*DKK];
__device__ float g_X[BB*LL*DD];       // attention output (B,L,D) fp32

// m16n8k16 bf16 MMA. A row-major (16x16), B col-major (16x8), C fp32.
__device__ __forceinline__ void mma16(float* c, const unsigned* a, unsigned b0, unsigned b1) {
    asm volatile(
        "mma.sync.aligned.m16n8k16.row.col.f32.bf16.bf16.f32 "
        "{%0,%1,%2,%3}, {%4,%5,%6,%7}, {%8,%9}, {%0,%1,%2,%3};\n"
        : "+f"(c[0]), "+f"(c[1]), "+f"(c[2]), "+f"(c[3])
        : "r"(a[0]), "r"(a[1]), "r"(a[2]), "r"(a[3]), "r"(b0), "r"(b1));
}

__device__ __forceinline__ unsigned packbf(float lo_val, float hi_val) {
    unsigned d;
    asm("cvt.rn.bf16x2.f32 %0, %1, %2;" : "=r"(d) : "f"(hi_val), "f"(lo_val));
    return d;
}
__device__ __forceinline__ void splitbf2(float xe, float xo, unsigned& h, unsigned& l) {
    h = packbf(xe, xo);
    float fe = __uint_as_float(h << 16);
    float fo = __uint_as_float(h & 0xffff0000u);
    l = packbf(xe - fe, xo - fo);
}

__device__ __forceinline__ float ex2f(float x) {
    float r;
    asm("ex2.approx.f32 %0, %1;" : "=f"(r) : "f"(x));
    return r;
}

__device__ __forceinline__ void cpa16(unsigned dst, const void* src) {
    asm volatile("cp.async.ca.shared.global [%0], [%1], 16;\n" :: "r"(dst), "l"(src));
}
__device__ __forceinline__ void cpa_commit() {
    asm volatile("cp.async.commit_group;\n");
}
template <int N>
__device__ __forceinline__ void cpa_wait() {
    asm volatile("cp.async.wait_group %0;\n" :: "n"(N));
}

// ---------------------------------------------------------------------------
// 3xBF16 GEMM (R6-proven, unchanged): C[m,n] = sum_k A[m,k]*W[n,k] + bias[n]
// ---------------------------------------------------------------------------
#define GP 20

__global__ __launch_bounds__(256) void gemm_bf16(
    const float* __restrict__ A, const float* __restrict__ W,
    const float* __restrict__ bias, float* __restrict__ C, int headmode)
{
    __shared__ unsigned Ah[128*GP], Al[128*GP], Bh[64*GP], Bl[64*GP];

    const int tid  = threadIdx.x;
    const int lane = tid & 31;
    const int warp = tid >> 5;
    const int g = lane >> 2, t = lane & 3;
    const int wm = warp & 3, wn = warp >> 2;
    const int m0 = blockIdx.y << 7, n0 = blockIdx.x << 6;

    float c[2][4][4];
    #pragma unroll
    for (int mt = 0; mt < 2; mt++)
        #pragma unroll
        for (int nt = 0; nt < 4; nt++)
            #pragma unroll
            for (int k = 0; k < 4; k++) c[mt][nt][k] = 0.f;

    const float* Abase = A + (size_t)m0 * DD;
    const float* Wbase = W + (size_t)n0 * DD;

    float4 ra[4], rb[2];
    #pragma unroll
    for (int i = 0; i < 4; i++) {
        int idx = tid + (i << 8);
        ra[i] = *(const float4*)(Abase + (size_t)(idx >> 3) * DD + ((idx & 7) << 2));
    }
    #pragma unroll
    for (int i = 0; i < 2; i++) {
        int idx = tid + (i << 8);
        rb[i] = *(const float4*)(Wbase + (size_t)(idx >> 3) * DD + ((idx & 7) << 2));
    }

    for (int k0 = 0; k0 < DD; k0 += 32) {
        __syncthreads();
        #pragma unroll
        for (int i = 0; i < 4; i++) {
            int idx = tid + (i << 8);
            int row = idx >> 3, kp = (idx & 7) << 1;
            unsigned h0, l0, h1, l1;
            splitbf2(ra[i].x, ra[i].y, h0, l0);
            splitbf2(ra[i].z, ra[i].w, h1, l1);
            *(uint2*)&Ah[row*GP + kp] = make_uint2(h0, h1);
            *(uint2*)&Al[row*GP + kp] = make_uint2(l0, l1);
        }
        #pragma unroll
        for (int i = 0; i < 2; i++) {
            int idx = tid + (i << 8);
            int row = idx >> 3, kp = (idx & 7) << 1;
            unsigned h0, l0, h1, l1;
            splitbf2(rb[i].x, rb[i].y, h0, l0);
            splitbf2(rb[i].z, rb[i].w, h1, l1);
            *(uint2*)&Bh[row*GP + kp] = make_uint2(h0, h1);
            *(uint2*)&Bl[row*GP + kp] = make_uint2(l0, l1);
        }
        __syncthreads();

        if (k0 + 32 < DD) {
            #pragma unroll
            for (int i = 0; i < 4; i++) {
                int idx = tid + (i << 8);
                ra[i] = *(const float4*)(Abase + (size_t)(idx >> 3) * DD + k0 + 32 + ((idx & 7) << 2));
            }
            #pragma unroll
            for (int i = 0; i < 2; i++) {
                int idx = tid + (i << 8);
                rb[i] = *(const float4*)(Wbase + (size_t)(idx >> 3) * DD + k0 + 32 + ((idx & 7) << 2));
            }
        }

        #pragma unroll
        for (int kt = 0; kt < 2; kt++) {
            unsigned ah[2][4], al[2][4];
            #pragma unroll
            for (int mt = 0; mt < 2; mt++) {
                int r = wm * 32 + mt * 16 + g;
                ah[mt][0] = Ah[ r      *GP + kt*8 + t    ];
                ah[mt][1] = Ah[(r + 8) *GP + kt*8 + t    ];
                ah[mt][2] = Ah[ r      *GP + kt*8 + t + 4];
                ah[mt][3] = Ah[(r + 8) *GP + kt*8 + t + 4];
                al[mt][0] = Al[ r      *GP + kt*8 + t    ];
                al[mt][1] = Al[(r + 8) *GP + kt*8 + t    ];
                al[mt][2] = Al[ r      *GP + kt*8 + t + 4];
                al[mt][3] = Al[(r + 8) *GP + kt*8 + t + 4];
            }
            #pragma unroll
            for (int nt = 0; nt < 4; nt++) {
                int r = wn * 32 + nt * 8 + g;
                unsigned bh0 = Bh[r*GP + kt*8 + t    ];
                unsigned bh1 = Bh[r*GP + kt*8 + t + 4];
                unsigned bl0 = Bl[r*GP + kt*8 + t    ];
                unsigned bl1 = Bl[r*GP + kt*8 + t + 4];
                #pragma unroll
                for (int mt = 0; mt < 2; mt++) {
                    mma16(c[mt][nt], al[mt], bh0, bh1);
                    mma16(c[mt][nt], ah[mt], bl0, bl1);
                    mma16(c[mt][nt], ah[mt], bh0, bh1);
                }
            }
        }
    }

    #pragma unroll
    for (int nt = 0; nt < 4; nt++) {
        int n = n0 + wn * 32 + nt * 8 + 2 * t;
        float b0 = bias[n], b1 = bias[n + 1];
        #pragma unroll
        for (int mt = 0; mt < 2; mt++) {
            int m = m0 + wm * 32 + mt * 16 + g;
            if (headmode) {
                int b_ = m >> 10, l = m & 1023;
                int h = n >> 6, dk = n & 63;
                float* p0 = C + (((size_t)b_ * HH + h) * LL + l) * DKK + dk;
                float* p1 = C + (((size_t)b_ * HH + h) * LL + (l + 8)) * DKK + dk;
                *(float2*)p0 = make_float2(c[mt][nt][0] + b0, c[mt][nt][1] + b1);
                *(float2*)p1 = make_float2(c[mt][nt][2] + b0, c[mt][nt][3] + b1);
            } else {
                float* p0 = C + (size_t)m * DD + n;
                float* p1 = C + (size_t)(m + 8) * DD + n;
                *(float2*)p0 = make_float2(c[mt][nt][0] + b0, c[mt][nt][1] + b1);
                *(float2*)p1 = make_float2(c[mt][nt][2] + b0, c[mt][nt][3] + b1);
            }
        }
    }
}

// ---------------------------------------------------------------------------
// Flash attention: cp.async double-buffered raw K/V, split-at-consumer,
// in-register P, base-2 softmax. Block = (bh, 64 q-rows), 128 thr (4 warps).
// smem: 2 x (Kraw[64][72] + Vraw[64][68]) fp32 = 71,680 B.
// ---------------------------------------------------------------------------
#define KRP 72
#define VRP 68
#define BUFW (64*KRP + 64*VRP)                    // 8960 floats per buffer
#define SMEM_ATTN (2 * BUFW * (int)sizeof(float)) // 71,680 B
#define LOG2E 1.4426950408889634f

__global__ __launch_bounds__(128, 3) void attn_bf16(
    const float* __restrict__ dist, const unsigned char* __restrict__ mask,
    const float* __restrict__ logwb)
{
    extern __shared__ float smf[];

    const int tid  = threadIdx.x;
    const int lane = tid & 31;
    const int warp = tid >> 5;
    const int g = lane >> 2, t = lane & 3;

    const int bh = blockIdx.y;
    const int b  = bh >> 3, h = bh & 7;
    const int q0 = blockIdx.x << 6;

    const float wb = __expf(logwb[h]) * LOG2E;   // base-2 folded bias weight

    const float* Kg = g_K + (size_t)bh * LL * DKK;
    const float* Vg = g_V + (size_t)bh * LL * DKK;
    const float* db = dist + (size_t)b * LL * LL;
    const unsigned char* mb = mask + (size_t)b * LL * LL;

    const unsigned smem_u32 = (unsigned)__cvta_generic_to_shared(smf);

    // --- prefetch tile 0 into buffer 0 ---
    {
        unsigned kb = smem_u32;
        unsigned vb = smem_u32 + 64*KRP*4;
        for (int i = tid; i < 1024; i += 128) {
            int r = i >> 4, c4 = (i & 15) << 2;
            cpa16(kb + (r*KRP + c4)*4, Kg + (size_t)r * DKK + c4);
            cpa16(vb + (r*VRP + c4)*4, Vg + (size_t)r * DKK + c4);
        }
        cpa_commit();
    }

    // --- Q fragments straight from gmem (scaled by 0.125*log2e) ---
    unsigned qh[4][4], ql[4][4];
    {
        const float qscale = 0.125f * LOG2E;
        const float* Qp  = g_Q + ((size_t)bh * LL + q0 + warp*16 + g) * DKK;
        const float* Qp8 = Qp + 8 * DKK;
        #pragma unroll
        for (int kt = 0; kt < 4; kt++) {
            int cb = kt*16 + 2*t;
            float2 f;
            f = *(const float2*)(Qp  + cb);     splitbf2(f.x*qscale, f.y*qscale, qh[kt][0], ql[kt][0]);
            f = *(const float2*)(Qp8 + cb);     splitbf2(f.x*qscale, f.y*qscale, qh[kt][1], ql[kt][1]);
            f = *(const float2*)(Qp  + cb + 8); splitbf2(f.x*qscale, f.y*qscale, qh[kt][2], ql[kt][2]);
            f = *(const float2*)(Qp8 + cb + 8); splitbf2(f.x*qscale, f.y*qscale, qh[kt][3], ql[kt][3]);
        }
    }

    float o[8][4];
    #pragma unroll
    for (int nt = 0; nt < 8; nt++)
        #pragma unroll
        for (int k = 0; k < 4; k++) o[nt][k] = 0.f;
    float mrow[2] = {-1e30f, -1e30f};
    float lrow[2] = {0.f, 0.f};

    const int qr0 = q0 + warp * 16 + g;

    for (int it = 0; it < 16; it++) {
        const int k0 = it << 6;
        float* Kr = smf + (it & 1) * BUFW;
        float* Vr = Kr + 64*KRP;

        if (it + 1 < 16) {
            int nb = (it + 1) & 1;
            unsigned kb = smem_u32 + nb * BUFW * 4;
            unsigned vb = kb + 64*KRP*4;
            const float* Kn = Kg + (size_t)(k0 + 64) * DKK;
            const float* Vn = Vg + (size_t)(k0 + 64) * DKK;
            for (int i = tid; i < 1024; i += 128) {
                int r = i >> 4, c4 = (i & 15) << 2;
                cpa16(kb + (r*KRP + c4)*4, Kn + (size_t)r * DKK + c4);
                cpa16(vb + (r*VRP + c4)*4, Vn + (size_t)r * DKK + c4);
            }
            cpa_commit();
            cpa_wait<1>();   // current tile landed; next still in flight
        } else {
            cpa_wait<0>();
        }
        __syncthreads();

        // hoisted dist/mask loads (in flight during S-MMA loop)
        float2 d0a[8], d1a[8];
        unsigned short mk0a[8], mk1a[8];
        #pragma unroll
        for (int nt = 0; nt < 8; nt++) {
            int col = k0 + nt*8 + 2*t;
            d0a[nt] = *(const float2*)(db + (size_t)qr0 * LL + col);
            d1a[nt] = *(const float2*)(db + (size_t)(qr0 + 8) * LL + col);
            mk0a[nt] = *(const unsigned short*)(mb + (size_t)qr0 * LL + col);
            mk1a[nt] = *(const unsigned short*)(mb + (size_t)(qr0 + 8) * LL + col);
        }

        // S = Q @ K^T (3xBF16, split-at-consumer)
        float s[8][4];
        #pragma unroll
        for (int nt = 0; nt < 8; nt++)
            #pragma unroll
            for (int k = 0; k < 4; k++) s[nt][k] = 0.f;

        #pragma unroll
        for (int kt = 0; kt < 4; kt++) {
            #pragma unroll
            for (int nt = 0; nt < 8; nt++) {
                const float* kp_ = Kr + (nt*8 + g) * KRP + kt*16 + 2*t;
                float2 ka = *(const float2*)kp_;
                float2 kb2 = *(const float2*)(kp_ + 8);
                unsigned bh0, bl0, bh1, bl1;
                splitbf2(ka.x, ka.y, bh0, bl0);
                splitbf2(kb2.x, kb2.y, bh1, bl1);
                mma16(s[nt], ql[kt], bh0, bh1);
                mma16(s[nt], qh[kt], bl0, bl1);
                mma16(s[nt], qh[kt], bh0, bh1);
            }
        }

        // distance bias + mask (base-2 domain; scores already carry log2e)
        #pragma unroll
        for (int nt = 0; nt < 8; nt++) {
            s[nt][0] -= d0a[nt].x * wb; if (mk0a[nt] & 0xffu) s[nt][0] = -1e9f;
            s[nt][1] -= d0a[nt].y * wb; if (mk0a[nt] >> 8)    s[nt][1] = -1e9f;
            s[nt][2] -= d1a[nt].x * wb; if (mk1a[nt] & 0xffu) s[nt][2] = -1e9f;
            s[nt][3] -= d1a[nt].y * wb; if (mk1a[nt] >> 8)    s[nt][3] = -1e9f;
        }

        // online softmax (base 2)
        #pragma unroll
        for (int i = 0; i < 2; i++) {
            float mx = -1e30f;
            #pragma unroll
            for (int nt = 0; nt < 8; nt++)
                mx = fmaxf(mx, fmaxf(s[nt][2*i], s[nt][2*i + 1]));
            mx = fmaxf(mx, __shfl_xor_sync(0xffffffffu, mx, 1));
            mx = fmaxf(mx, __shfl_xor_sync(0xffffffffu, mx, 2));
            float mnew  = fmaxf(mrow[i], mx);
            float alpha = ex2f(mrow[i] - mnew);
            float sum = 0.f;
            #pragma unroll
            for (int nt = 0; nt < 8; nt++) {
                s[nt][2*i]     = ex2f(s[nt][2*i]     - mnew);
                s[nt][2*i + 1] = ex2f(s[nt][2*i + 1] - mnew);
                sum += s[nt][2*i] + s[nt][2*i + 1];
            }
            sum += __shfl_xor_sync(0xffffffffu, sum, 1);
            sum += __shfl_xor_sync(0xffffffffu, sum, 2);
            lrow[i] = lrow[i] * alpha + sum;
            mrow[i] = mnew;
            #pragma unroll
            for (int nt = 0; nt < 8; nt++) {
                o[nt][2*i]     *= alpha;
                o[nt][2*i + 1] *= alpha;
            }
        }

        // O += P @ V (3xBF16); P A-frags via in-lane permutation (validated R7/R8)
        #pragma unroll
        for (int kt = 0; kt < 4; kt++) {
            unsigned pah[4], pal[4];
            splitbf2(s[2*kt  ][0], s[2*kt  ][1], pah[0], pal[0]);
            splitbf2(s[2*kt  ][2], s[2*kt  ][3], pah[1], pal[1]);
            splitbf2(s[2*kt+1][0], s[2*kt+1][1], pah[2], pal[2]);
            splitbf2(s[2*kt+1][2], s[2*kt+1][3], pah[3], pal[3]);
            #pragma unroll
            for (int nt = 0; nt < 8; nt++) {
                const float* vp = Vr + (kt*16 + 2*t) * VRP + nt*8 + g;
                unsigned vh0, vl0, vh1, vl1;
                splitbf2(vp[0],      vp[VRP],   vh0, vl0);
                splitbf2(vp[8*VRP],  vp[9*VRP], vh1, vl1);
                mma16(o[nt], pah, vl0, vl1);
                mma16(o[nt], pal, vh0, vh1);
                mma16(o[nt], pah, vh0, vh1);
            }
        }
        __syncthreads();   // done reading this buffer; free for tile it+2
    }

    // normalize + write X (B,L,D)
    float inv0 = 1.0f / lrow[0], inv1 = 1.0f / lrow[1];
    float* X0 = g_X + ((size_t)b * LL + qr0)     * DD + h * DKK;
    float* X1 = g_X + ((size_t)b * LL + qr0 + 8) * DD + h * DKK;
    #pragma unroll
    for (int nt = 0; nt < 8; nt++) {
        *(float2*)&X0[nt*8 + 2*t] = make_float2(o[nt][0] * inv0, o[nt][1] * inv0);
        *(float2*)&X1[nt*8 + 2*t] = make_float2(o[nt][2] * inv1, o[nt][3] * inv1);
    }
}

// ---------------------------------------------------------------------------
extern "C" void kernel_launch(void* const* d_in, const int* in_sizes, int n_in,
                              void* d_out, int out_size)
{
    const float* query = (const float*)d_in[0];
    const float* key   = (const float*)d_in[1];
    const float* value = (const float*)d_in[2];
    const float* dist  = (const float*)d_in[3];
    const unsigned char* mask = (const unsigned char*)d_in[4];
    const float* Wq = (const float*)d_in[5];
    const float* bq = (const float*)d_in[6];
    const float* Wk = (const float*)d_in[7];
    const float* bk = (const float*)d_in[8];
    const float* Wv = (const float*)d_in[9];
    const float* bv = (const float*)d_in[10];
    const float* Wo = (const float*)d_in[11];
    const float* bo = (const float*)d_in[12];
    const float* logwb = (const float*)d_in[13];

    void *pQ, *pK, *pV, *pX;
    cudaGetSymbolAddress(&pQ, g_Q);
    cudaGetSymbolAddress(&pK, g_K);
    cudaGetSymbolAddress(&pV, g_V);
    cudaGetSymbolAddress(&pX, g_X);

    cudaFuncSetAttribute(attn_bf16,
                         cudaFuncAttributeMaxDynamicSharedMemorySize, SMEM_ATTN);

    dim3 gg(DD / 64, (BB * LL) / 128);   // (8, 64)
    gemm_bf16<<<gg, 256>>>(query, Wq, bq, (float*)pQ, 1);
    gemm_bf16<<<gg, 256>>>(key,   Wk, bk, (float*)pK, 1);
    gemm_bf16<<<gg, 256>>>(value, Wv, bv, (float*)pV, 1);

    attn_bf16<<<dim3(LL / 64, BB * HH), 128, SMEM_ATTN>>>(dist, mask, logwb);

    gemm_bf16<<<gg, 256>>>((const float*)pX, Wo, bo, (float*)d_out, 0);
}